// round 13
// baseline (speedup 1.0000x reference)
#include <cuda_runtime.h>

// out = outer(w, x) @ x0 + bias + x  ==  w * dot(x, x0) + bias + x
// D = 8192 floats = 2048 float4.
// R13: 8 CTAs x 128 threads (4 warps = 1/SMSP). Each CTA redundantly computes
// the full dot. Fatter threads (16 float4/vector each, 34 front-batched LDGs,
// still < per-warp MLP cap ~55) buy a minimal inter-warp stage: 4 warp sums,
// one barrier with only 4 arrivals, single broadcast LDS.128 + 2-deep fold.

#define NCTAS 8
#define NTHR  128
#define NWARP (NTHR / 32)             // 4
#define V4_TOTAL 2048
#define V4_PER_T (V4_TOTAL / NTHR)    // 16 float4 per vector per thread
#define V4_PER_CTA (V4_TOTAL / NCTAS) // 256 -> 2 float4 per thread epilogue

__global__ void __launch_bounds__(NTHR) cross_fused_kernel(const float4* __restrict__ x0,
                                                           const float4* __restrict__ x,
                                                           const float4* __restrict__ w,
                                                           const float4* __restrict__ b,
                                                           float4* __restrict__ out) {
    const int t = threadIdx.x;

    // ---- Front-batch ALL loads (32 dot LDG.128 + 4 epilogue LDG.128, plus
    //      epilogue x comes from the dot registers) ----
    float4 a[V4_PER_T], xv[V4_PER_T];
    #pragma unroll
    for (int k = 0; k < V4_PER_T; k++) {
        a[k]  = x0[t + k * NTHR];
        xv[k] = x[t + k * NTHR];
    }
    const int e0 = blockIdx.x * V4_PER_CTA + t;        // epilogue elem 0
    const int e1 = e0 + NTHR;                          // epilogue elem 1
    float4 wv0 = w[e0], wv1 = w[e1];
    float4 bv0 = b[e0], bv1 = b[e1];

    // Epilogue x values come from the dot-phase registers:
    // x[e0] = xv[blockIdx.x*2], x[e1] = xv[blockIdx.x*2 + 1].
    float4 xe0 = xv[0], xe1 = xv[1];
    #pragma unroll
    for (int k = 1; k < NCTAS; k++) {
        if (blockIdx.x == (unsigned)k) { xe0 = xv[2 * k]; xe1 = xv[2 * k + 1]; }
    }

    // Epilogue additive parts — independent of the reduction.
    float4 cv0, cv1;
    cv0.x = bv0.x + xe0.x; cv0.y = bv0.y + xe0.y;
    cv0.z = bv0.z + xe0.z; cv0.w = bv0.w + xe0.w;
    cv1.x = bv1.x + xe1.x; cv1.y = bv1.y + xe1.y;
    cv1.z = bv1.z + xe1.z; cv1.w = bv1.w + xe1.w;

    // ---- Partial dot: 16 per-float4 partials, 4-deep tree fold ----
    float p[V4_PER_T];
    #pragma unroll
    for (int k = 0; k < V4_PER_T; k++) {
        p[k] = (a[k].x * xv[k].x + a[k].y * xv[k].y)
             + (a[k].z * xv[k].z + a[k].w * xv[k].w);
    }
    float s = (((p[0]  + p[1])  + (p[2]  + p[3]))
             + ((p[4]  + p[5])  + (p[6]  + p[7])))
            + (((p[8]  + p[9])  + (p[10] + p[11]))
             + ((p[12] + p[13]) + (p[14] + p[15])));

    // ---- Warp reduction (5 shfl) ----
    #pragma unroll
    for (int o = 16; o > 0; o >>= 1)
        s += __shfl_xor_sync(0xFFFFFFFFu, s, o);

    __shared__ float4 ws4[1];           // 4 warp sums in one float4
    float* ws = (float*)ws4;
    const int warp = t >> 5;
    const int lane = t & 31;
    if (lane == 0) ws[warp] = s;
    __syncthreads();

    // Single broadcast LDS.128 + 2-deep fold.
    float4 u = ws4[0];
    const float sv = (u.x + u.y) + (u.z + u.w);

    // ---- Epilogue: out = w*s + (b + x), 2 float4 per thread ----
    float4 o0, o1;
    o0.x = fmaf(wv0.x, sv, cv0.x);
    o0.y = fmaf(wv0.y, sv, cv0.y);
    o0.z = fmaf(wv0.z, sv, cv0.z);
    o0.w = fmaf(wv0.w, sv, cv0.w);
    o1.x = fmaf(wv1.x, sv, cv1.x);
    o1.y = fmaf(wv1.y, sv, cv1.y);
    o1.z = fmaf(wv1.z, sv, cv1.z);
    o1.w = fmaf(wv1.w, sv, cv1.w);
    out[e0] = o0;
    out[e1] = o1;
}

extern "C" void kernel_launch(void* const* d_in, const int* in_sizes, int n_in,
                              void* d_out, int out_size) {
    const float4* x0 = (const float4*)d_in[0];
    const float4* x  = (const float4*)d_in[1];
    const float4* w  = (const float4*)d_in[2];
    const float4* b  = (const float4*)d_in[3];
    float4* out = (float4*)d_out;

    cross_fused_kernel<<<NCTAS, NTHR>>>(x0, x, w, b, out);
}

// round 14
// speedup vs baseline: 1.1077x; 1.1077x over previous
#include <cuda_runtime.h>

// out = outer(w, x) @ x0 + bias + x  ==  w * dot(x, x0) + bias + x
// D = 8192 floats = 2048 float4.
// TERMINAL FORM (R6, best measured 6.56us): 8 CTAs x 256 threads, single
// launch, one barrier. Each CTA redundantly computes the full dot (no
// inter-CTA dependency, no global scratch). All loads front-batched (19
// independent LDG.128 -> one memory latency at full MLP). 5-shfl warp
// reduction; 8 warp sums broadcast-folded via 2x LDS.128.
//
// Session evidence: every structural perturbation (1/8/16 CTAs; 128/256/512/
// 1024 threads; packed f32x2; truncated shuffle; load elimination; 2-kernel
// split) measured 6.62-6.91us. Wall time is dominated by a fixed
// launch/replay floor (~6.4us, T_ovh ~5000 cyc at un-ramped clocks); this
// kernel sits at the measured minimum of the controllable T_CTA term.

#define NCTAS 8
#define NTHR  256
#define NWARP (NTHR / 32)
#define V4_TOTAL 2048
#define V4_PER_T (V4_TOTAL / NTHR)    // 8
#define V4_PER_CTA (V4_TOTAL / NCTAS) // 256

__global__ void __launch_bounds__(NTHR) cross_fused_kernel(const float4* __restrict__ x0,
                                                           const float4* __restrict__ x,
                                                           const float4* __restrict__ w,
                                                           const float4* __restrict__ b,
                                                           float4* __restrict__ out) {
    const int t = threadIdx.x;

    // ---- Front-batch ALL loads (19 independent LDG.128) ----
    float4 a[V4_PER_T], xv[V4_PER_T];
    #pragma unroll
    for (int k = 0; k < V4_PER_T; k++) {
        a[k]  = x0[t + k * NTHR];
        xv[k] = x[t + k * NTHR];
    }
    const int ei = blockIdx.x * V4_PER_CTA + t;
    float4 wv = w[ei];
    float4 bv = b[ei];
    float4 xe = x[ei];

    // Epilogue additive part is independent of the reduction — fold early.
    float4 cv;
    cv.x = bv.x + xe.x;
    cv.y = bv.y + xe.y;
    cv.z = bv.z + xe.z;
    cv.w = bv.w + xe.w;

    // ---- Partial dot ----
    float s = 0.f;
    #pragma unroll
    for (int k = 0; k < V4_PER_T; k++) {
        s += a[k].x * xv[k].x + a[k].y * xv[k].y
           + a[k].z * xv[k].z + a[k].w * xv[k].w;
    }

    // Warp reduction (5 shfl)
    #pragma unroll
    for (int o = 16; o > 0; o >>= 1)
        s += __shfl_xor_sync(0xFFFFFFFFu, s, o);

    __shared__ float4 ws4[NWARP / 4];   // 8 warp sums as 2 float4 for LDS.128
    float* ws = (float*)ws4;
    const int warp = t >> 5;
    const int lane = t & 31;
    if (lane == 0) ws[warp] = s;
    __syncthreads();

    // Every thread: broadcast-load all 8 warp sums (2x LDS.128), sum locally.
    float4 u0 = ws4[0];
    float4 u1 = ws4[1];
    const float sv = ((u0.x + u0.y) + (u0.z + u0.w))
                   + ((u1.x + u1.y) + (u1.z + u1.w));

    // ---- Epilogue: out = w*s + (b + x) ----
    float4 o;
    o.x = fmaf(wv.x, sv, cv.x);
    o.y = fmaf(wv.y, sv, cv.y);
    o.z = fmaf(wv.z, sv, cv.z);
    o.w = fmaf(wv.w, sv, cv.w);
    out[ei] = o;
}

extern "C" void kernel_launch(void* const* d_in, const int* in_sizes, int n_in,
                              void* d_out, int out_size) {
    const float4* x0 = (const float4*)d_in[0];
    const float4* x  = (const float4*)d_in[1];
    const float4* w  = (const float4*)d_in[2];
    const float4* b  = (const float4*)d_in[3];
    float4* out = (float4*)d_out;

    cross_fused_kernel<<<NCTAS, NTHR>>>(x0, x, w, b, out);
}